// round 7
// baseline (speedup 1.0000x reference)
#include <cuda_runtime.h>

#define NUM_USERS 100000
#define NUM_ITEMS 200000
#define NN        300000
#define NNZ_E     2000000
#define F2        32                 // float2 elements per 64-float row

#define SCAN_T    256
#define SCAN_E    1024               // 4 elements per thread
#define SCAN_NB   ((NN + SCAN_E - 1) / SCAN_E)   // 293

// ---- static device scratch (allocation-free rule) ----
__device__ float2 g_e1[(size_t)NN * F2];
__device__ float2 g_e2[(size_t)NN * F2];
__device__ int    g_rowptr[NN + 1];
__device__ int    g_cur[NN];
__device__ int2   g_edges[NNZ_E];    // {col, float_as_int(val)} bucketed by row
__device__ int    g_blksum[SCAN_NB];

// ---------------------------------------------------------------------------
__global__ void zero_rowptr_kernel() {
    int i = blockIdx.x * blockDim.x + threadIdx.x;
    if (i <= NN) g_rowptr[i] = 0;
}

__global__ void hist_kernel(const int* __restrict__ rows) {
    int e = blockIdx.x * blockDim.x + threadIdx.x;
    if (e < NNZ_E) atomicAdd(&g_rowptr[__ldg(rows + e)], 1);
}

// Block-local exclusive scan (4 elems/thread), in place; block sums out.
__global__ void scan1_kernel() {
    __shared__ int sh[SCAN_T];
    int b = blockIdx.x, t = threadIdx.x;
    int base = b * SCAN_E + t * 4;
    int v[4]; int s = 0;
#pragma unroll
    for (int k = 0; k < 4; k++) {
        int idx = base + k;
        v[k] = (idx < NN) ? g_rowptr[idx] : 0;
        s += v[k];
    }
    sh[t] = s; __syncthreads();
    for (int off = 1; off < SCAN_T; off <<= 1) {
        int x = (t >= off) ? sh[t - off] : 0;
        __syncthreads();
        sh[t] += x;
        __syncthreads();
    }
    if (t == SCAN_T - 1) g_blksum[b] = sh[t];
    int run = sh[t] - s;
#pragma unroll
    for (int k = 0; k < 4; k++) {
        int idx = base + k;
        if (idx < NN) g_rowptr[idx] = run;
        run += v[k];
    }
}

__global__ void scan2_kernel() {
    __shared__ int sh[512];
    int t = threadIdx.x;
    int v = (t < SCAN_NB) ? g_blksum[t] : 0;
    sh[t] = v; __syncthreads();
    for (int off = 1; off < 512; off <<= 1) {
        int x = (t >= off) ? sh[t - off] : 0;
        __syncthreads();
        sh[t] += x;
        __syncthreads();
    }
    if (t < SCAN_NB) g_blksum[t] = sh[t] - v;
}

__global__ void scan3_kernel() {
    int i = blockIdx.x * blockDim.x + threadIdx.x;
    if (i < NN) {
        int r = g_rowptr[i] + g_blksum[i / SCAN_E];
        g_rowptr[i] = r;
        g_cur[i]    = r;
    }
    if (i == 0) g_rowptr[NN] = NNZ_E;
}

__global__ void bucket_kernel(const float* __restrict__ vals,
                              const int*   __restrict__ rows,
                              const int*   __restrict__ cols) {
    int e = blockIdx.x * blockDim.x + threadIdx.x;
    if (e >= NNZ_E) return;
    int r   = __ldg(rows + e);
    int pos = atomicAdd(&g_cur[r], 1);
    g_edges[pos] = make_int2(__ldg(cols + e), __float_as_int(__ldg(vals + e)));
}

// ---------------------------------------------------------------------------
// Warp-per-row CSR SpMM. 32 lanes × float2 = one 256B row.
// Edges batch-loaded cooperatively (one coalesced 8B/lane load), then each
// edge broadcast via shfl -> all gather addresses available early (high MLP).
// FIRST: gather from user/item tables directly (no ego copy).
// LAST : fuse out = (e0 + e1 + e2 + e3) / 4, skip storing e3.
// ---------------------------------------------------------------------------
template <bool FIRST, bool LAST>
__global__ void __launch_bounds__(256)
spmm_warp_kernel(const float2* __restrict__ src,
                 const float2* __restrict__ user,
                 const float2* __restrict__ item,
                 float2* __restrict__ dst) {
    int r  = (blockIdx.x * blockDim.x + threadIdx.x) >> 5;   // warp -> row
    int ln = threadIdx.x & 31;
    if (r >= NN) return;

    int s = __ldg(&g_rowptr[r]);
    int e = __ldg(&g_rowptr[r + 1]);

    float ax = 0.f, ay = 0.f;
    for (int base = s; base < e; base += 32) {
        int cnt = e - base;
        if (cnt > 32) cnt = 32;
        int2 ed = make_int2(0, 0);
        if (ln < cnt) ed = __ldg(&g_edges[base + ln]);
#pragma unroll 4
        for (int j = 0; j < cnt; j++) {
            int   c = __shfl_sync(0xffffffffu, ed.x, j);
            float v = __int_as_float(__shfl_sync(0xffffffffu, ed.y, j));
            float2 x;
            if (FIRST)
                x = (c < NUM_USERS) ? __ldg(user + (size_t)c * F2 + ln)
                                    : __ldg(item + (size_t)(c - NUM_USERS) * F2 + ln);
            else
                x = __ldg(src + (size_t)c * F2 + ln);
            ax = fmaf(v, x.x, ax);
            ay = fmaf(v, x.y, ay);
        }
    }

    size_t o = (size_t)r * F2 + ln;
    if (LAST) {
        float2 e0 = (r < NUM_USERS) ? __ldg(user + o)
                                    : __ldg(item + o - (size_t)NUM_USERS * F2);
        float2 a = __ldg(&g_e1[o]);
        float2 b = __ldg(&g_e2[o]);
        float2 oo;
        oo.x = (e0.x + a.x + b.x + ax) * 0.25f;
        oo.y = (e0.y + a.y + b.y + ay) * 0.25f;
        dst[o] = oo;
    } else {
        __stcs(dst + o, make_float2(ax, ay));   // evict-first: keep src in L2
    }
}

// ---------------------------------------------------------------------------
extern "C" void kernel_launch(void* const* d_in, const int* in_sizes, int n_in,
                              void* d_out, int out_size) {
    const float2* user = (const float2*)d_in[0];
    const float2* item = (const float2*)d_in[1];
    const float*  vals = (const float*)d_in[2];
    const int*    rows = (const int*)d_in[3];
    const int*    cols = (const int*)d_in[4];
    float2*       out  = (float2*)d_out;

    void *p1, *p2;
    cudaGetSymbolAddress(&p1, g_e1);
    cudaGetSymbolAddress(&p2, g_e2);
    float2* E1 = (float2*)p1;
    float2* E2 = (float2*)p2;

    const int T = 256;
    const int gZero  = (NN + 1 + T - 1) / T;
    const int gEdge  = (NNZ_E + T - 1) / T;
    const int gScan3 = (NN + T - 1) / T;
    const int gRow   = (NN * 32 + T - 1) / T;   // 1 warp per row -> 37500 blocks

    // --- CSR build ---
    zero_rowptr_kernel<<<gZero, T>>>();
    hist_kernel<<<gEdge, T>>>(rows);
    scan1_kernel<<<SCAN_NB, SCAN_T>>>();
    scan2_kernel<<<1, 512>>>();
    scan3_kernel<<<gScan3, T>>>();
    bucket_kernel<<<gEdge, T>>>(vals, rows, cols);

    // --- 3 propagation layers; layer 3 fused with accumulate/normalize ---
    spmm_warp_kernel<true,  false><<<gRow, T>>>(nullptr, user, item, E1);
    spmm_warp_kernel<false, false><<<gRow, T>>>(E1, nullptr, nullptr, E2);
    spmm_warp_kernel<false, true ><<<gRow, T>>>(E2, user, item, out);
}

// round 8
// speedup vs baseline: 1.2491x; 1.2491x over previous
#include <cuda_runtime.h>

#define NUM_USERS 100000
#define NUM_ITEMS 200000
#define NN        300000
#define EMB       64
#define VEC       (EMB / 4)          // 16 float4 per row
#define NNZ_E     2000000

#define SCAN_T    256
#define SCAN_E    1024               // 4 elements per thread
#define SCAN_NB   ((NN + SCAN_E - 1) / SCAN_E)   // 293

// ---- static device scratch (allocation-free rule) ----
__device__ float4 g_e1[(size_t)NN * VEC];
__device__ float4 g_e2[(size_t)NN * VEC];
__device__ int    g_rowptr[NN + 1];
__device__ int    g_cur[NN];
__device__ int2   g_edges[NNZ_E];    // {col, float_as_int(val)} bucketed by row
__device__ int    g_blksum[SCAN_NB];

// ---------------------------------------------------------------------------
__global__ void zero_rowptr_kernel() {
    int i = blockIdx.x * blockDim.x + threadIdx.x;
    if (i <= NN) g_rowptr[i] = 0;
}

__global__ void hist_kernel(const int* __restrict__ rows) {
    int e = blockIdx.x * blockDim.x + threadIdx.x;
    if (e < NNZ_E) atomicAdd(&g_rowptr[__ldg(rows + e)], 1);
}

// Block-local exclusive scan (4 elems/thread), in place; block sums out.
__global__ void scan1_kernel() {
    __shared__ int sh[SCAN_T];
    int b = blockIdx.x, t = threadIdx.x;
    int base = b * SCAN_E + t * 4;
    int v[4]; int s = 0;
#pragma unroll
    for (int k = 0; k < 4; k++) {
        int idx = base + k;
        v[k] = (idx < NN) ? g_rowptr[idx] : 0;
        s += v[k];
    }
    sh[t] = s; __syncthreads();
    for (int off = 1; off < SCAN_T; off <<= 1) {
        int x = (t >= off) ? sh[t - off] : 0;
        __syncthreads();
        sh[t] += x;
        __syncthreads();
    }
    if (t == SCAN_T - 1) g_blksum[b] = sh[t];
    int run = sh[t] - s;
#pragma unroll
    for (int k = 0; k < 4; k++) {
        int idx = base + k;
        if (idx < NN) g_rowptr[idx] = run;
        run += v[k];
    }
}

__global__ void scan2_kernel() {
    __shared__ int sh[512];
    int t = threadIdx.x;
    int v = (t < SCAN_NB) ? g_blksum[t] : 0;
    sh[t] = v; __syncthreads();
    for (int off = 1; off < 512; off <<= 1) {
        int x = (t >= off) ? sh[t - off] : 0;
        __syncthreads();
        sh[t] += x;
        __syncthreads();
    }
    if (t < SCAN_NB) g_blksum[t] = sh[t] - v;
}

__global__ void scan3_kernel() {
    int i = blockIdx.x * blockDim.x + threadIdx.x;
    if (i < NN) {
        int r = g_rowptr[i] + g_blksum[i / SCAN_E];
        g_rowptr[i] = r;
        g_cur[i]    = r;
    }
    if (i == 0) g_rowptr[NN] = NNZ_E;
}

__global__ void bucket_kernel(const float* __restrict__ vals,
                              const int*   __restrict__ rows,
                              const int*   __restrict__ cols) {
    int e = blockIdx.x * blockDim.x + threadIdx.x;
    if (e >= NNZ_E) return;
    int r   = __ldg(rows + e);
    int pos = atomicAdd(&g_cur[r], 1);
    g_edges[pos] = make_int2(__ldg(cols + e), __float_as_int(__ldg(vals + e)));
}

// ---------------------------------------------------------------------------
// CSR SpMM: 16 threads per row, float4 per thread, register accumulation,
// streaming store. Edge loads are half-warp broadcasts (single transaction).
// FIRST: gather from user/item tables directly (no ego copy).
// LAST : fuse out = (e0 + e1 + e2 + e3) / 4; e3 never stored.
// ---------------------------------------------------------------------------
template <bool FIRST, bool LAST>
__global__ void __launch_bounds__(256)
spmm_csr_kernel(const float4* __restrict__ src,
                const float4* __restrict__ user,
                const float4* __restrict__ item,
                float4* __restrict__ dst) {
    int t  = blockIdx.x * blockDim.x + threadIdx.x;
    int r  = t >> 4;
    int ln = t & 15;
    if (r >= NN) return;

    int s = __ldg(&g_rowptr[r]);
    int e = __ldg(&g_rowptr[r + 1]);

    float4 acc = make_float4(0.f, 0.f, 0.f, 0.f);
    for (int k = s; k < e; k++) {
        int2  ed = __ldg(&g_edges[k]);
        int   c  = ed.x;
        float v  = __int_as_float(ed.y);
        float4 x;
        if (FIRST)
            x = (c < NUM_USERS) ? __ldg(user + (size_t)c * VEC + ln)
                                : __ldg(item + (size_t)(c - NUM_USERS) * VEC + ln);
        else
            x = __ldg(src + (size_t)c * VEC + ln);
        acc.x = fmaf(v, x.x, acc.x);
        acc.y = fmaf(v, x.y, acc.y);
        acc.z = fmaf(v, x.z, acc.z);
        acc.w = fmaf(v, x.w, acc.w);
    }

    size_t o = (size_t)r * VEC + ln;
    if (LAST) {
        float4 e0 = (r < NUM_USERS) ? __ldg(user + o)
                                    : __ldg(item + o - (size_t)NUM_USERS * VEC);
        float4 a = __ldg(&g_e1[o]);
        float4 b = __ldg(&g_e2[o]);
        float4 oo;
        oo.x = (e0.x + a.x + b.x + acc.x) * 0.25f;
        oo.y = (e0.y + a.y + b.y + acc.y) * 0.25f;
        oo.z = (e0.z + a.z + b.z + acc.z) * 0.25f;
        oo.w = (e0.w + a.w + b.w + acc.w) * 0.25f;
        dst[o] = oo;
    } else {
        __stcs(dst + o, acc);   // evict-first: keep src resident in L2
    }
}

// ---------------------------------------------------------------------------
extern "C" void kernel_launch(void* const* d_in, const int* in_sizes, int n_in,
                              void* d_out, int out_size) {
    const float4* user = (const float4*)d_in[0];
    const float4* item = (const float4*)d_in[1];
    const float*  vals = (const float*)d_in[2];
    const int*    rows = (const int*)d_in[3];
    const int*    cols = (const int*)d_in[4];
    float4*       out  = (float4*)d_out;

    void *p1, *p2;
    cudaGetSymbolAddress(&p1, g_e1);
    cudaGetSymbolAddress(&p2, g_e2);
    float4* E1 = (float4*)p1;
    float4* E2 = (float4*)p2;

    const int T = 256;
    const int gZero  = (NN + 1 + T - 1) / T;
    const int gEdge  = (NNZ_E + T - 1) / T;
    const int gScan3 = (NN + T - 1) / T;
    const int gRow   = (NN * VEC + T - 1) / T;   // 18750 blocks

    // --- CSR build ---
    zero_rowptr_kernel<<<gZero, T>>>();
    hist_kernel<<<gEdge, T>>>(rows);
    scan1_kernel<<<SCAN_NB, SCAN_T>>>();
    scan2_kernel<<<1, 512>>>();
    scan3_kernel<<<gScan3, T>>>();
    bucket_kernel<<<gEdge, T>>>(vals, rows, cols);

    // --- 3 propagation layers; layer 3 fused with accumulate/normalize ---
    spmm_csr_kernel<true,  false><<<gRow, T>>>(nullptr, user, item, E1);
    spmm_csr_kernel<false, false><<<gRow, T>>>(E1, nullptr, nullptr, E2);
    spmm_csr_kernel<false, true ><<<gRow, T>>>(E2, user, item, out);
}

// round 9
// speedup vs baseline: 1.6264x; 1.3021x over previous
#include <cuda_runtime.h>
#include <cuda_fp16.h>

#define NUM_USERS 100000
#define NUM_ITEMS 200000
#define NN        300000
#define NNZ_E     2000000
#define VEC       16                 // 16 × float4  = 256B fp32 row
#define HV        16                 // 16 × uint2(4 halfs) = 128B fp16 row

#define SCAN_T    256
#define SCAN_E    1024
#define SCAN_NB   ((NN + SCAN_E - 1) / SCAN_E)   // 293

// ---- static device scratch (allocation-free rule) ----
__device__ uint2  g_h0[(size_t)NN * HV];   // fp16 ego embeddings   (38.4 MB)
__device__ uint2  g_h1[(size_t)NN * HV];   // fp16 layer-1 output
__device__ uint2  g_h2[(size_t)NN * HV];   // fp16 layer-2 output
__device__ int    g_rowptr[NN + 1];
__device__ int    g_cur[NN];
__device__ int2   g_edges[NNZ_E];          // {col, val bits} bucketed by row
__device__ int    g_blksum[SCAN_NB];

// ---- fp16 pack/unpack helpers ----
__device__ __forceinline__ unsigned f2h(float a, float b) {
    __half2 h = __floats2half2_rn(a, b);
    return *reinterpret_cast<unsigned*>(&h);
}
__device__ __forceinline__ float2 h2f(unsigned u) {
    __half2 h = *reinterpret_cast<__half2*>(&u);
    return __half22float2(h);
}

// ---------------------------------------------------------------------------
// Convert fp32 inputs -> packed fp16 ego table (row-major, 4 halfs / thread).
// ---------------------------------------------------------------------------
__global__ void convert_kernel(const float4* __restrict__ user,
                               const float4* __restrict__ item) {
    int i = blockIdx.x * blockDim.x + threadIdx.x;
    if (i >= NN * VEC) return;
    float4 v = (i < NUM_USERS * VEC) ? __ldg(user + i)
                                     : __ldg(item + i - NUM_USERS * VEC);
    uint2 u;
    u.x = f2h(v.x, v.y);
    u.y = f2h(v.z, v.w);
    g_h0[i] = u;
}

// ---------------------------------------------------------------------------
__global__ void zero_rowptr_kernel() {
    int i = blockIdx.x * blockDim.x + threadIdx.x;
    if (i <= NN) g_rowptr[i] = 0;
}

__global__ void hist_kernel(const int* __restrict__ rows) {
    int e = blockIdx.x * blockDim.x + threadIdx.x;
    if (e < NNZ_E) atomicAdd(&g_rowptr[__ldg(rows + e)], 1);
}

__global__ void scan1_kernel() {
    __shared__ int sh[SCAN_T];
    int b = blockIdx.x, t = threadIdx.x;
    int base = b * SCAN_E + t * 4;
    int v[4]; int s = 0;
#pragma unroll
    for (int k = 0; k < 4; k++) {
        int idx = base + k;
        v[k] = (idx < NN) ? g_rowptr[idx] : 0;
        s += v[k];
    }
    sh[t] = s; __syncthreads();
    for (int off = 1; off < SCAN_T; off <<= 1) {
        int x = (t >= off) ? sh[t - off] : 0;
        __syncthreads();
        sh[t] += x;
        __syncthreads();
    }
    if (t == SCAN_T - 1) g_blksum[b] = sh[t];
    int run = sh[t] - s;
#pragma unroll
    for (int k = 0; k < 4; k++) {
        int idx = base + k;
        if (idx < NN) g_rowptr[idx] = run;
        run += v[k];
    }
}

__global__ void scan2_kernel() {
    __shared__ int sh[512];
    int t = threadIdx.x;
    int v = (t < SCAN_NB) ? g_blksum[t] : 0;
    sh[t] = v; __syncthreads();
    for (int off = 1; off < 512; off <<= 1) {
        int x = (t >= off) ? sh[t - off] : 0;
        __syncthreads();
        sh[t] += x;
        __syncthreads();
    }
    if (t < SCAN_NB) g_blksum[t] = sh[t] - v;
}

__global__ void scan3_kernel() {
    int i = blockIdx.x * blockDim.x + threadIdx.x;
    if (i < NN) {
        int r = g_rowptr[i] + g_blksum[i / SCAN_E];
        g_rowptr[i] = r;
        g_cur[i]    = r;
    }
    if (i == 0) g_rowptr[NN] = NNZ_E;
}

__global__ void bucket_kernel(const float* __restrict__ vals,
                              const int*   __restrict__ rows,
                              const int*   __restrict__ cols) {
    int e = blockIdx.x * blockDim.x + threadIdx.x;
    if (e >= NNZ_E) return;
    int r   = __ldg(rows + e);
    int pos = atomicAdd(&g_cur[r], 1);
    g_edges[pos] = make_int2(__ldg(cols + e), __float_as_int(__ldg(vals + e)));
}

// ---------------------------------------------------------------------------
// CSR SpMM over fp16 rows: 16 threads/row, 4 features (one uint2 = 8B) per
// thread, fp32 accumulation, fp16 streaming store.
// LAST: fuse out = (e0_fp32 + e1 + e2 + acc) / 4 as fp32 float4.
// ---------------------------------------------------------------------------
template <bool LAST>
__global__ void __launch_bounds__(256)
spmm_h_kernel(const uint2* __restrict__ src,
              const float4* __restrict__ user,
              const float4* __restrict__ item,
              uint2* __restrict__ dsth,
              float4* __restrict__ out) {
    int t  = blockIdx.x * blockDim.x + threadIdx.x;
    int r  = t >> 4;
    int ln = t & 15;
    if (r >= NN) return;

    int s = __ldg(&g_rowptr[r]);
    int e = __ldg(&g_rowptr[r + 1]);

    float ax = 0.f, ay = 0.f, az = 0.f, aw = 0.f;
    for (int k = s; k < e; k++) {
        int2  ed = __ldg(&g_edges[k]);
        int   c  = ed.x;
        float v  = __int_as_float(ed.y);
        uint2 xu = __ldg(src + (size_t)c * HV + ln);
        float2 f0 = h2f(xu.x);
        float2 f1 = h2f(xu.y);
        ax = fmaf(v, f0.x, ax);
        ay = fmaf(v, f0.y, ay);
        az = fmaf(v, f1.x, az);
        aw = fmaf(v, f1.y, aw);
    }

    size_t o = (size_t)r * HV + ln;
    if (LAST) {
        float4 e0 = (r < NUM_USERS)
                  ? __ldg(user + (size_t)r * VEC + ln)
                  : __ldg(item + (size_t)(r - NUM_USERS) * VEC + ln);
        uint2 u1 = __ldg(&g_h1[o]);
        uint2 u2 = __ldg(&g_h2[o]);
        float2 a0 = h2f(u1.x), a1 = h2f(u1.y);
        float2 b0 = h2f(u2.x), b1 = h2f(u2.y);
        float4 oo;
        oo.x = (e0.x + a0.x + b0.x + ax) * 0.25f;
        oo.y = (e0.y + a0.y + b0.y + ay) * 0.25f;
        oo.z = (e0.z + a1.x + b1.x + az) * 0.25f;
        oo.w = (e0.w + a1.y + b1.y + aw) * 0.25f;
        out[(size_t)r * VEC + ln] = oo;
    } else {
        uint2 u;
        u.x = f2h(ax, ay);
        u.y = f2h(az, aw);
        __stcs(dsth + o, u);    // evict-first: keep src table resident in L2
    }
}

// ---------------------------------------------------------------------------
extern "C" void kernel_launch(void* const* d_in, const int* in_sizes, int n_in,
                              void* d_out, int out_size) {
    const float4* user = (const float4*)d_in[0];
    const float4* item = (const float4*)d_in[1];
    const float*  vals = (const float*)d_in[2];
    const int*    rows = (const int*)d_in[3];
    const int*    cols = (const int*)d_in[4];
    float4*       out  = (float4*)d_out;

    void *p0, *p1, *p2;
    cudaGetSymbolAddress(&p0, g_h0);
    cudaGetSymbolAddress(&p1, g_h1);
    cudaGetSymbolAddress(&p2, g_h2);
    uint2* H0 = (uint2*)p0;
    uint2* H1 = (uint2*)p1;
    uint2* H2 = (uint2*)p2;

    const int T = 256;
    const int gZero  = (NN + 1 + T - 1) / T;
    const int gEdge  = (NNZ_E + T - 1) / T;
    const int gScan3 = (NN + T - 1) / T;
    const int gRow   = (NN * 16 + T - 1) / T;   // 18750 blocks

    // --- fp16 ego table + CSR build ---
    convert_kernel<<<gRow, T>>>(user, item);
    zero_rowptr_kernel<<<gZero, T>>>();
    hist_kernel<<<gEdge, T>>>(rows);
    scan1_kernel<<<SCAN_NB, SCAN_T>>>();
    scan2_kernel<<<1, 512>>>();
    scan3_kernel<<<gScan3, T>>>();
    bucket_kernel<<<gEdge, T>>>(vals, rows, cols);

    // --- 3 propagation layers (fp16 gathers, fp32 accumulation) ---
    spmm_h_kernel<false><<<gRow, T>>>(H0, nullptr, nullptr, H1, nullptr);
    spmm_h_kernel<false><<<gRow, T>>>(H1, nullptr, nullptr, H2, nullptr);
    spmm_h_kernel<true ><<<gRow, T>>>(H2, user, item, nullptr, out);
}